// round 15
// baseline (speedup 1.0000x reference)
#include <cuda_runtime.h>
#include <cuda_fp16.h>
#include <cstdint>

// DAS beamform, round 13: fp16 staging + TMA bulk group fills.
//   - half2 lerp with 4 INDEPENDENT accumulator pairs (r12's issue savings
//     without its serial dependency chain), flushed to f32 per 4-ch group.
//   - only warp 0 waits on the fill mbarrier; bar.sync publishes CTA-wide.
//   - prefetch bulk issued immediately after the barrier (max latency cover).

#define NC      128
#define NS      2048
#define NPIX    65536
#define THREADS 1024
#define PX_PER_BLOCK 886
#define TILES_PER_BATCH 74
#define GRID    (2 * TILES_PER_BATCH)   // 148

#define CH_BYTES   (NS * 8)             // 16 KB per channel (fp16, K=4)
#define GRP_CH     4
#define GRP_BYTES  (GRP_CH * CH_BYTES)  // 64 KB per group
#define NGRP       (NC / GRP_CH)        // 32 iterations
#define SPR_OFF_B  (3 * GRP_BYTES)              // 196608
#define MBAR_OFF_B (SPR_OFF_B + NC * 16)        // 198656 (pr as float4)
#define SMEM_BYTES (MBAR_OFF_B + 3 * 8)

// fp16 copy of rf: [B, Nc, Ns, K] halves = 4 MB (module scratch, allowed)
__device__ __align__(16) __half RF16[2 * NC * NS * 4];

__global__ __launch_bounds__(256)
void conv_kernel(const float4* __restrict__ rf4)
{
    const int idx = blockIdx.x * blockDim.x + threadIdx.x;   // 0 .. 262143
    const float4 a = rf4[2 * idx];
    const float4 b = rf4[2 * idx + 1];
    __half2 h0 = __float22half2_rn(make_float2(a.x, a.y));
    __half2 h1 = __float22half2_rn(make_float2(a.z, a.w));
    __half2 h2 = __float22half2_rn(make_float2(b.x, b.y));
    __half2 h3 = __float22half2_rn(make_float2(b.z, b.w));
    uint4 o;
    o.x = *reinterpret_cast<uint32_t*>(&h0);
    o.y = *reinterpret_cast<uint32_t*>(&h1);
    o.z = *reinterpret_cast<uint32_t*>(&h2);
    o.w = *reinterpret_cast<uint32_t*>(&h3);
    reinterpret_cast<uint4*>(RF16)[idx] = o;
}

__device__ __forceinline__ uint32_t smem_u32(const void* p) {
    uint32_t a;
    asm("{ .reg .u64 t; cvta.to.shared.u64 t, %1; cvt.u32.u64 %0, t; }"
        : "=r"(a) : "l"(p));
    return a;
}

__device__ __forceinline__ void mbar_init(uint32_t mbar, uint32_t count) {
    asm volatile("mbarrier.init.shared.b64 [%0], %1;" :: "r"(mbar), "r"(count) : "memory");
}

__device__ __forceinline__ void mbar_expect_tx(uint32_t mbar, uint32_t bytes) {
    asm volatile("mbarrier.arrive.expect_tx.shared.b64 _, [%0], %1;"
                 :: "r"(mbar), "r"(bytes) : "memory");
}

__device__ __forceinline__ void bulk_g2s(uint32_t dst, const void* src,
                                         uint32_t bytes, uint32_t mbar) {
    asm volatile(
        "cp.async.bulk.shared::cta.global.mbarrier::complete_tx::bytes "
        "[%0], [%1], %2, [%3];"
        :: "r"(dst), "l"(src), "r"(bytes), "r"(mbar) : "memory");
}

__device__ __forceinline__ void mbar_wait(uint32_t mbar, uint32_t parity) {
    uint32_t done;
    asm volatile(
        "{\n\t"
        ".reg .pred p;\n\t"
        "mbarrier.try_wait.parity.acquire.cta.shared::cta.b64 p, [%1], %2;\n\t"
        "selp.b32 %0, 1, 0, p;\n\t"
        "}"
        : "=r"(done) : "r"(mbar), "r"(parity) : "memory");
    if (!done) {
        asm volatile(
            "{\n\t"
            ".reg .pred P1;\n\t"
            "WAIT_LOOP_%=:\n\t"
            "mbarrier.try_wait.parity.acquire.cta.shared::cta.b64 P1, [%0], %1, 0x989680;\n\t"
            "@P1 bra.uni WAIT_DONE_%=;\n\t"
            "bra.uni WAIT_LOOP_%=;\n\t"
            "WAIT_DONE_%=:\n\t"
            "}"
            :: "r"(mbar), "r"(parity) : "memory");
    }
}

__global__ __launch_bounds__(THREADS, 1)
void das_kernel(const float* __restrict__ g,
                const float* __restrict__ pr,
                const float* __restrict__ p,
                float* __restrict__ out)
{
    extern __shared__ char smem[];
    float4* spr4 = reinterpret_cast<float4*>(smem + SPR_OFF_B);

    const int tid  = threadIdx.x;
    const int wid  = tid >> 5;
    const int b    = blockIdx.x / TILES_PER_BATCH;
    const int tile = blockIdx.x % TILES_PER_BATCH;
    const int pix0 = tile * PX_PER_BLOCK + tid;
    const bool active = (tid < PX_PER_BLOCK) && (pix0 < NPIX);
    const int pix  = active ? pix0 : 0;

    const uint32_t smem_base = smem_u32(smem);
    const uint32_t mbar_base = smem_base + MBAR_OFF_B;

    if (tid == 0) {
        mbar_init(mbar_base + 0, 1);
        mbar_init(mbar_base + 8, 1);
        mbar_init(mbar_base + 16, 1);
    }
    if (tid < NC) {
        float4 v;
        v.x = pr[b * NC * 3 + tid * 3 + 0];
        v.y = pr[b * NC * 3 + tid * 3 + 1];
        v.z = pr[b * NC * 3 + tid * 3 + 2];
        v.w = 0.0f;
        spr4[tid] = v;
    }

    const float c0 = p[b * 4 + 0];
    const float fs = p[b * 4 + 1];
    const float t0 = p[b * 4 + 2];
    const float scale = fs / c0;
    const float gx = g[((size_t)b * NPIX + pix) * 3 + 0];
    const float gy = g[((size_t)b * NPIX + pix) * 3 + 1];
    const float gz = g[((size_t)b * NPIX + pix) * 3 + 2];
    const float sbase = scale * (t0 + gz);

    const char* rf_base = reinterpret_cast<const char*>(RF16) + (size_t)b * NC * CH_BYTES;

    __syncthreads();   // mbar init + spr visible

    if (tid == 0) {
        mbar_expect_tx(mbar_base + 0, GRP_BYTES);
        bulk_g2s(smem_base + 0 * GRP_BYTES, rf_base + (size_t)0 * GRP_BYTES, GRP_BYTES, mbar_base + 0);
        mbar_expect_tx(mbar_base + 8, GRP_BYTES);
        bulk_g2s(smem_base + 1 * GRP_BYTES, rf_base + (size_t)1 * GRP_BYTES, GRP_BYTES, mbar_base + 8);
    }

    float accx = 0.f, accy = 0.f, accz = 0.f, accw = 0.f;

    int slot = 0;
    int phase = 0;

    #pragma unroll 1
    for (int t = 0; t < NGRP; t++) {
        const int c = t * GRP_CH;

        // only warp 0 polls the fill mbarrier; the CTA barrier below both
        // publishes the TMA data to all threads and guarantees every thread
        // finished reading ring slot (slot+2)%3 (last used at iter t-1).
        if (wid == 0) mbar_wait(mbar_base + slot * 8, (uint32_t)phase);
        __syncthreads();

        // prefetch group t+2 into slot (slot+2)%3 immediately: a full
        // iteration of compute now covers its fill latency.
        if (t + 2 < NGRP && tid == 0) {
            int fslot = slot + 2; if (fslot >= 3) fslot -= 3;
            mbar_expect_tx(mbar_base + fslot * 8, GRP_BYTES);
            bulk_g2s(smem_base + fslot * GRP_BYTES,
                     rf_base + (size_t)(t + 2) * GRP_BYTES,
                     GRP_BYTES, mbar_base + fslot * 8);
        }

        if (active) {
            const char* grp_ptr = smem + slot * GRP_BYTES;

            // 4 INDEPENDENT half2 accumulator pairs — no cross-channel chain.
            __half2 aLo0 = __float2half2_rn(0.f), aHi0 = __float2half2_rn(0.f);
            __half2 aLo1 = __float2half2_rn(0.f), aHi1 = __float2half2_rn(0.f);
            __half2 aLo2 = __float2half2_rn(0.f), aHi2 = __float2half2_rn(0.f);
            __half2 aLo3 = __float2half2_rn(0.f), aHi3 = __float2half2_rn(0.f);
            __half2* aLo[4] = { &aLo0, &aLo1, &aLo2, &aLo3 };
            __half2* aHi[4] = { &aHi0, &aHi1, &aHi2, &aHi3 };

            #pragma unroll
            for (int j = 0; j < GRP_CH; j++) {
                const float4 prc = spr4[c + j];      // LDS.128 broadcast

                const float dx = gx - prc.x;
                const float dy = gy - prc.y;
                const float dz = gz - prc.z;
                const float dd = fmaf(dx, dx, fmaf(dy, dy, dz * dz));
                float d; asm("sqrt.approx.f32 %0, %1;" : "=f"(d) : "f"(dd));
                float s = fmaf(scale, d, sbase);
                s = fminf(fmaxf(s, 0.0f), 2047.0f);
                int i0 = min((int)s, NS - 2);
                const float w  = s - (float)i0;
                const float w0 = 1.0f - w;
                const __half2 wh  = __float2half2_rn(w);
                const __half2 w0h = __float2half2_rn(w0);

                const uint2* buf = reinterpret_cast<const uint2*>(grp_ptr + j * CH_BYTES);
                uint2 r0 = buf[i0];
                uint2 r1 = buf[i0 + 1];

                const __half2 y0lo = *reinterpret_cast<__half2*>(&r0.x);
                const __half2 y0hi = *reinterpret_cast<__half2*>(&r0.y);
                const __half2 y1lo = *reinterpret_cast<__half2*>(&r1.x);
                const __half2 y1hi = *reinterpret_cast<__half2*>(&r1.y);

                *aLo[j] = __hfma2(w0h, y0lo, __hfma2(wh, y1lo, *aLo[j]));
                *aHi[j] = __hfma2(w0h, y0hi, __hfma2(wh, y1hi, *aHi[j]));
            }

            // flush the 4 channel partials to f32 accumulators
            const float2 l0 = __half22float2(aLo0), h0 = __half22float2(aHi0);
            const float2 l1 = __half22float2(aLo1), h1 = __half22float2(aHi1);
            const float2 l2 = __half22float2(aLo2), h2 = __half22float2(aHi2);
            const float2 l3 = __half22float2(aLo3), h3 = __half22float2(aHi3);
            accx += (l0.x + l1.x) + (l2.x + l3.x);
            accy += (l0.y + l1.y) + (l2.y + l3.y);
            accz += (h0.x + h1.x) + (h2.x + h3.x);
            accw += (h0.y + h1.y) + (h2.y + h3.y);
        }

        if (++slot == 3) { slot = 0; phase ^= 1; }
    }

    if (active) {
        float4 r;
        r.x = accx; r.y = accy; r.z = accz; r.w = accw;
        reinterpret_cast<float4*>(out)[(size_t)b * NPIX + pix0] = r;
    }
}

extern "C" void kernel_launch(void* const* d_in, const int* in_sizes, int n_in,
                              void* d_out, int out_size)
{
    const float* rf = (const float*)d_in[0];
    const float* g  = (const float*)d_in[1];
    const float* pr = (const float*)d_in[2];
    const float* p  = (const float*)d_in[3];
    float* out = (float*)d_out;

    conv_kernel<<<1024, 256>>>(reinterpret_cast<const float4*>(rf));

    cudaFuncSetAttribute(das_kernel, cudaFuncAttributeMaxDynamicSharedMemorySize, SMEM_BYTES);
    das_kernel<<<GRID, THREADS, SMEM_BYTES>>>(g, pr, p, out);
}

// round 17
// speedup vs baseline: 1.5622x; 1.5622x over previous
#include <cuda_runtime.h>
#include <cuda_fp16.h>
#include <cstdint>

// DAS beamform, round 16: r11 structure (best: 37.2us kernel) + half2 lerp
// with 4 independent register-array accumulators.
//   - ring of 3 x 64KB slots (4 channels/group), one bulk/wait/barrier per group
//   - ALL threads poll the fill mbarrier (r11 behavior; elect-one regressed)
//   - prefetch issued after compute+barrier (r11 placement)
//   - lerp in HFMA2, per-group flush to f32 (bounds fp16 error; rel_err ~4e-4)

#define NC      128
#define NS      2048
#define NPIX    65536
#define THREADS 1024
#define PX_PER_BLOCK 886
#define TILES_PER_BATCH 74
#define GRID    (2 * TILES_PER_BATCH)   // 148

#define CH_BYTES   (NS * 8)             // 16 KB per channel (fp16, K=4)
#define GRP_CH     4
#define GRP_BYTES  (GRP_CH * CH_BYTES)  // 64 KB per group
#define NGRP       (NC / GRP_CH)        // 32 iterations
#define SPR_OFF_B  (3 * GRP_BYTES)              // 196608
#define MBAR_OFF_B (SPR_OFF_B + NC * 16)        // 198656 (pr as float4)
#define SMEM_BYTES (MBAR_OFF_B + 3 * 8)

// fp16 copy of rf: [B, Nc, Ns, K] halves = 4 MB (module scratch, allowed)
__device__ __align__(16) __half RF16[2 * NC * NS * 4];

__global__ __launch_bounds__(256)
void conv_kernel(const float4* __restrict__ rf4)
{
    const int idx = blockIdx.x * blockDim.x + threadIdx.x;   // 0 .. 262143
    const float4 a = rf4[2 * idx];
    const float4 b = rf4[2 * idx + 1];
    __half2 h0 = __float22half2_rn(make_float2(a.x, a.y));
    __half2 h1 = __float22half2_rn(make_float2(a.z, a.w));
    __half2 h2 = __float22half2_rn(make_float2(b.x, b.y));
    __half2 h3 = __float22half2_rn(make_float2(b.z, b.w));
    uint4 o;
    o.x = *reinterpret_cast<uint32_t*>(&h0);
    o.y = *reinterpret_cast<uint32_t*>(&h1);
    o.z = *reinterpret_cast<uint32_t*>(&h2);
    o.w = *reinterpret_cast<uint32_t*>(&h3);
    reinterpret_cast<uint4*>(RF16)[idx] = o;
}

__device__ __forceinline__ uint32_t smem_u32(const void* p) {
    uint32_t a;
    asm("{ .reg .u64 t; cvta.to.shared.u64 t, %1; cvt.u32.u64 %0, t; }"
        : "=r"(a) : "l"(p));
    return a;
}

__device__ __forceinline__ void mbar_init(uint32_t mbar, uint32_t count) {
    asm volatile("mbarrier.init.shared.b64 [%0], %1;" :: "r"(mbar), "r"(count) : "memory");
}

__device__ __forceinline__ void mbar_expect_tx(uint32_t mbar, uint32_t bytes) {
    asm volatile("mbarrier.arrive.expect_tx.shared.b64 _, [%0], %1;"
                 :: "r"(mbar), "r"(bytes) : "memory");
}

__device__ __forceinline__ void bulk_g2s(uint32_t dst, const void* src,
                                         uint32_t bytes, uint32_t mbar) {
    asm volatile(
        "cp.async.bulk.shared::cta.global.mbarrier::complete_tx::bytes "
        "[%0], [%1], %2, [%3];"
        :: "r"(dst), "l"(src), "r"(bytes), "r"(mbar) : "memory");
}

__device__ __forceinline__ void mbar_wait(uint32_t mbar, uint32_t parity) {
    uint32_t done;
    asm volatile(
        "{\n\t"
        ".reg .pred p;\n\t"
        "mbarrier.try_wait.parity.acquire.cta.shared::cta.b64 p, [%1], %2;\n\t"
        "selp.b32 %0, 1, 0, p;\n\t"
        "}"
        : "=r"(done) : "r"(mbar), "r"(parity) : "memory");
    if (!done) {
        asm volatile(
            "{\n\t"
            ".reg .pred P1;\n\t"
            "WAIT_LOOP_%=:\n\t"
            "mbarrier.try_wait.parity.acquire.cta.shared::cta.b64 P1, [%0], %1, 0x989680;\n\t"
            "@P1 bra.uni WAIT_DONE_%=;\n\t"
            "bra.uni WAIT_LOOP_%=;\n\t"
            "WAIT_DONE_%=:\n\t"
            "}"
            :: "r"(mbar), "r"(parity) : "memory");
    }
}

__global__ __launch_bounds__(THREADS, 1)
void das_kernel(const float* __restrict__ g,
                const float* __restrict__ pr,
                const float* __restrict__ p,
                float* __restrict__ out)
{
    extern __shared__ char smem[];
    float4* spr4 = reinterpret_cast<float4*>(smem + SPR_OFF_B);

    const int tid  = threadIdx.x;
    const int b    = blockIdx.x / TILES_PER_BATCH;
    const int tile = blockIdx.x % TILES_PER_BATCH;
    const int pix0 = tile * PX_PER_BLOCK + tid;
    const bool active = (tid < PX_PER_BLOCK) && (pix0 < NPIX);
    const int pix  = active ? pix0 : 0;

    const uint32_t smem_base = smem_u32(smem);
    const uint32_t mbar_base = smem_base + MBAR_OFF_B;

    if (tid == 0) {
        mbar_init(mbar_base + 0, 1);
        mbar_init(mbar_base + 8, 1);
        mbar_init(mbar_base + 16, 1);
    }
    if (tid < NC) {
        float4 v;
        v.x = pr[b * NC * 3 + tid * 3 + 0];
        v.y = pr[b * NC * 3 + tid * 3 + 1];
        v.z = pr[b * NC * 3 + tid * 3 + 2];
        v.w = 0.0f;
        spr4[tid] = v;
    }

    const float c0 = p[b * 4 + 0];
    const float fs = p[b * 4 + 1];
    const float t0 = p[b * 4 + 2];
    const float scale = fs / c0;
    const float gx = g[((size_t)b * NPIX + pix) * 3 + 0];
    const float gy = g[((size_t)b * NPIX + pix) * 3 + 1];
    const float gz = g[((size_t)b * NPIX + pix) * 3 + 2];
    const float sbase = scale * (t0 + gz);

    const char* rf_base = reinterpret_cast<const char*>(RF16) + (size_t)b * NC * CH_BYTES;

    __syncthreads();   // mbar init + spr visible

    if (tid == 0) {
        mbar_expect_tx(mbar_base + 0, GRP_BYTES);
        bulk_g2s(smem_base + 0 * GRP_BYTES, rf_base + (size_t)0 * GRP_BYTES, GRP_BYTES, mbar_base + 0);
        mbar_expect_tx(mbar_base + 8, GRP_BYTES);
        bulk_g2s(smem_base + 1 * GRP_BYTES, rf_base + (size_t)1 * GRP_BYTES, GRP_BYTES, mbar_base + 8);
    }

    float accx = 0.f, accy = 0.f, accz = 0.f, accw = 0.f;

    int slot = 0;
    int phase = 0;

    #pragma unroll 1
    for (int t = 0; t < NGRP; t++) {
        const int c = t * GRP_CH;

        if (active) {
            mbar_wait(mbar_base + slot * 8, (uint32_t)phase);  // all threads (r11)

            const char* grp_ptr = smem + slot * GRP_BYTES;

            // 4 independent half2 accumulator pairs, plain arrays with
            // constant indices under full unroll -> register promoted.
            __half2 aLo[GRP_CH], aHi[GRP_CH];
            #pragma unroll
            for (int j = 0; j < GRP_CH; j++) {
                aLo[j] = __float2half2_rn(0.f);
                aHi[j] = __float2half2_rn(0.f);
            }

            #pragma unroll
            for (int j = 0; j < GRP_CH; j++) {
                const float4 prc = spr4[c + j];      // LDS.128 broadcast

                const float dx = gx - prc.x;
                const float dy = gy - prc.y;
                const float dz = gz - prc.z;
                const float dd = fmaf(dx, dx, fmaf(dy, dy, dz * dz));
                float d; asm("sqrt.approx.f32 %0, %1;" : "=f"(d) : "f"(dd));
                float s = fmaf(scale, d, sbase);
                s = fminf(fmaxf(s, 0.0f), 2047.0f);
                int i0 = min((int)s, NS - 2);
                const float w  = s - (float)i0;
                const float w0 = 1.0f - w;
                const __half2 wh  = __float2half2_rn(w);
                const __half2 w0h = __float2half2_rn(w0);

                const uint2* buf = reinterpret_cast<const uint2*>(grp_ptr + j * CH_BYTES);
                uint2 r0 = buf[i0];
                uint2 r1 = buf[i0 + 1];

                const __half2 y0lo = *reinterpret_cast<__half2*>(&r0.x);
                const __half2 y0hi = *reinterpret_cast<__half2*>(&r0.y);
                const __half2 y1lo = *reinterpret_cast<__half2*>(&r1.x);
                const __half2 y1hi = *reinterpret_cast<__half2*>(&r1.y);

                aLo[j] = __hfma2(w0h, y0lo, __hfma2(wh, y1lo, aLo[j]));
                aHi[j] = __hfma2(w0h, y0hi, __hfma2(wh, y1hi, aHi[j]));
            }

            // flush group partials to f32 accumulators
            const float2 l0 = __half22float2(aLo[0]), h0 = __half22float2(aHi[0]);
            const float2 l1 = __half22float2(aLo[1]), h1 = __half22float2(aHi[1]);
            const float2 l2 = __half22float2(aLo[2]), h2 = __half22float2(aHi[2]);
            const float2 l3 = __half22float2(aLo[3]), h3 = __half22float2(aHi[3]);
            accx += (l0.x + l1.x) + (l2.x + l3.x);
            accy += (l0.y + l1.y) + (l2.y + l3.y);
            accz += (h0.x + h1.x) + (h2.x + h3.x);
            accw += (h0.y + h1.y) + (h2.y + h3.y);
        }

        // all reads of slot (slot+2)%3 complete before refill (r11 placement)
        __syncthreads();
        if (t + 2 < NGRP && tid == 0) {
            int fslot = slot + 2; if (fslot >= 3) fslot -= 3;
            mbar_expect_tx(mbar_base + fslot * 8, GRP_BYTES);
            bulk_g2s(smem_base + fslot * GRP_BYTES,
                     rf_base + (size_t)(t + 2) * GRP_BYTES,
                     GRP_BYTES, mbar_base + fslot * 8);
        }

        if (++slot == 3) { slot = 0; phase ^= 1; }
    }

    if (active) {
        float4 r;
        r.x = accx; r.y = accy; r.z = accz; r.w = accw;
        reinterpret_cast<float4*>(out)[(size_t)b * NPIX + pix0] = r;
    }
}

extern "C" void kernel_launch(void* const* d_in, const int* in_sizes, int n_in,
                              void* d_out, int out_size)
{
    const float* rf = (const float*)d_in[0];
    const float* g  = (const float*)d_in[1];
    const float* pr = (const float*)d_in[2];
    const float* p  = (const float*)d_in[3];
    float* out = (float*)d_out;

    conv_kernel<<<1024, 256>>>(reinterpret_cast<const float4*>(rf));

    cudaFuncSetAttribute(das_kernel, cudaFuncAttributeMaxDynamicSharedMemorySize, SMEM_BYTES);
    das_kernel<<<GRID, THREADS, SMEM_BYTES>>>(g, pr, p, out);
}